// round 9
// baseline (speedup 1.0000x reference)
#include <cuda_runtime.h>
#include <stdint.h>
#include <math.h>

#define S_LEN 2048
#define NH    8
#define NB    2
#define DH    64
#define NROWS (NB*NH*S_LEN)   // 32768
#define CAP   256
#define PT    68              // smem tile pitch (elements)

// ---- scratch (static device memory; zero-initialized at load) ----
__device__ int   g_rowmax[NROWS];
__device__ int   g_rowcnt[NROWS];
__device__ int   g_cidx[(size_t)NROWS * CAP];
__device__ float g_cval[(size_t)NROWS * CAP];

__device__ __forceinline__ uint32_t cvt_tf32(float x){
  uint32_t r;
  asm("cvt.rna.tf32.f32 %0, %1;" : "=r"(r) : "f"(x));
  return r;
}
__device__ __forceinline__ void mma_tf32(float* c, const uint32_t* a, uint32_t b0, uint32_t b1){
  asm volatile(
    "mma.sync.aligned.m16n8k8.row.col.f32.tf32.tf32.f32 "
    "{%0,%1,%2,%3}, {%4,%5,%6,%7}, {%8,%9}, {%0,%1,%2,%3};"
    : "+f"(c[0]), "+f"(c[1]), "+f"(c[2]), "+f"(c[3])
    : "r"(a[0]), "r"(a[1]), "r"(a[2]), "r"(a[3]), "r"(b0), "r"(b1));
}

// ===================== Kernel 1: tf32 mma.sync QK^T =====================
// Pure compute: per-row approx max + exact-recomputed candidates. No P writes.
__global__ __launch_bounds__(256, 2)
void qk_mma(const float* __restrict__ Q, const float* __restrict__ K,
            const int* __restrict__ mask, float* __restrict__ P)
{
  extern __shared__ char sm[];
  int* smask = (int*)sm;                                  // [128]
  uint32_t* Qs = (uint32_t*)(sm + 512);                   // [128][PT] tf32 bits
  uint32_t* Ks = (uint32_t*)(sm + 512 + 128 * PT * 4);    // [128][PT]

  const int bh = blockIdx.z;
  const int tm = blockIdx.y << 7;
  const int tn = blockIdx.x << 7;
  const int t = threadIdx.x;
  const int wid = t >> 5, lane = t & 31;
  const int wm = wid >> 1, wn = wid & 1;   // warps: 4 over M, 2 over N
  const int g  = lane >> 2, qd = lane & 3;
  const int b  = bh >> 3;
  const float* Qb = Q + ((size_t)bh * S_LEN + tm) * DH;
  const float* Kb = K + ((size_t)bh * S_LEN + tn) * DH;

  if (t < 128) smask[t] = mask[b * S_LEN + tn + t];

  // Load tiles, convert to tf32 (rna) into smem.
  #pragma unroll
  for (int i = 0; i < 8; i++){
    int idx = (i << 8) + t;            // 0..2047
    int row = idx >> 4;
    int col = (idx & 15) << 2;
    float4 q = *(const float4*)(Qb + row * DH + col);
    float4 k = *(const float4*)(Kb + row * DH + col);
    uint32_t* qd_ = Qs + row * PT + col;
    qd_[0] = cvt_tf32(q.x); qd_[1] = cvt_tf32(q.y);
    qd_[2] = cvt_tf32(q.z); qd_[3] = cvt_tf32(q.w);
    uint32_t* kd_ = Ks + row * PT + col;
    kd_[0] = cvt_tf32(k.x); kd_[1] = cvt_tf32(k.y);
    kd_[2] = cvt_tf32(k.z); kd_[3] = cvt_tf32(k.w);
  }
  __syncthreads();

  // Accumulators: 2 m-tiles x 8 n-tiles x 4 regs (warp tile 32x64).
  float c[2][8][4];
  #pragma unroll
  for (int mt = 0; mt < 2; mt++)
    #pragma unroll
    for (int nt = 0; nt < 8; nt++)
      #pragma unroll
      for (int j = 0; j < 4; j++) c[mt][nt][j] = 0.0f;

  #pragma unroll
  for (int ks = 0; ks < 8; ks++){
    const int k0 = ks << 3;
    uint32_t a[2][4];
    #pragma unroll
    for (int mt = 0; mt < 2; mt++){
      int rbase = (wm << 5) + (mt << 4) + g;
      a[mt][0] = Qs[ rbase      * PT + k0 + qd];
      a[mt][1] = Qs[(rbase + 8) * PT + k0 + qd];
      a[mt][2] = Qs[ rbase      * PT + k0 + qd + 4];
      a[mt][3] = Qs[(rbase + 8) * PT + k0 + qd + 4];
    }
    #pragma unroll
    for (int nt = 0; nt < 8; nt++){
      int nbase = (wn << 6) + (nt << 3) + g;
      uint32_t b0 = Ks[nbase * PT + k0 + qd];
      uint32_t b1 = Ks[nbase * PT + k0 + qd + 4];
      mma_tf32(c[0][nt], a[0], b0, b1);
      mma_tf32(c[1][nt], a[1], b0, b1);
    }
  }

  // Epilogue: per-row approx max -> atomicMax -> flags -> exact recompute.
  float ths[2][2];
  unsigned fl[2] = {0u, 0u};
  #pragma unroll
  for (int mt = 0; mt < 2; mt++){
    #pragma unroll
    for (int rr = 0; rr < 2; rr++){
      const int r = (wm << 5) + (mt << 4) + (rr << 3) + g;
      float lmax = -1e9f;
      #pragma unroll
      for (int nt = 0; nt < 8; nt++){
        int cb = (wn << 6) + (nt << 3) + (qd << 1);
        float v0 = c[mt][nt][rr * 2 + 0];
        float v1 = c[mt][nt][rr * 2 + 1];
        if (smask[cb])     lmax = fmaxf(lmax, v0);
        if (smask[cb + 1]) lmax = fmaxf(lmax, v1);
      }
      lmax = fmaxf(lmax, __shfl_xor_sync(0xffffffffu, lmax, 1));
      lmax = fmaxf(lmax, __shfl_xor_sync(0xffffffffu, lmax, 2));
      const int grow = bh * S_LEN + tm + r;
      float newmax = 0.0f;
      if (qd == 0){
        int old = atomicMax(&g_rowmax[grow], __float_as_int(lmax));
        newmax = fmaxf(lmax, __int_as_float(old));
      }
      newmax = __shfl_sync(0xffffffffu, newmax, lane & ~3);
      ths[mt][rr] = newmax - 0.19f;   // 0.03 slack + 2 x 0.065 tf32 margin
    }
  }
  #pragma unroll
  for (int mt = 0; mt < 2; mt++)
    #pragma unroll
    for (int nt = 0; nt < 8; nt++)
      #pragma unroll
      for (int rr = 0; rr < 2; rr++)
        #pragma unroll
        for (int jj = 0; jj < 2; jj++){
          int cb = (wn << 6) + (nt << 3) + (qd << 1) + jj;
          unsigned pred = (smask[cb] && c[mt][nt][rr * 2 + jj] >= ths[mt][rr]) ? 1u : 0u;
          int bit = (mt << 5) + (nt << 2) + (rr << 1) + jj;
          fl[bit >> 5] |= pred << (bit & 31);
        }

  #pragma unroll
  for (int wdi = 0; wdi < 2; wdi++){
    unsigned bits = fl[wdi];
    while (bits){
      int p = __ffs(bits) - 1; bits &= bits - 1;
      int code = (wdi << 5) + p;
      int mt = code >> 5, rem = code & 31;
      int nt = rem >> 2, rr = (rem >> 1) & 1, jj = rem & 1;
      int r  = (wm << 5) + (mt << 4) + (rr << 3) + g;
      int cc = (wn << 6) + (nt << 3) + (qd << 1) + jj;
      // exact fp32 recompute from global (L1/L2-hot)
      const float* qr = Qb + r * DH;
      const float* kr = Kb + cc * DH;
      float acc = 0.0f;
      #pragma unroll 16
      for (int d = 0; d < DH; d++) acc += qr[d] * kr[d];
      float ap = c[mt][nt][rr * 2 + jj];
      // sanity gate: if the MMA path is broken, insert nothing -> exact fallback
      if (fabsf(acc - ap) <= 0.5f){
        int grow = bh * S_LEN + tm + r;
        int pos = atomicAdd(&g_rowcnt[grow], 1);
        if (pos < CAP){
          g_cidx[(size_t)grow * CAP + pos] = tn + cc;
          g_cval[(size_t)grow * CAP + pos] = acc;
        }
      }
    }
  }
}

// ==== Kernel 2: warp-per-row — zero P row, candidate softmax + PV ====
__global__ __launch_bounds__(256)
void scatter_pv(const float* __restrict__ Q, const float* __restrict__ K,
                const float* __restrict__ V, const int* __restrict__ mask,
                float* __restrict__ P, float* __restrict__ Out)
{
  const int wid  = threadIdx.x >> 5;
  const int lane = threadIdx.x & 31;
  const int row  = (blockIdx.x << 3) + wid;
  const int bh   = row >> 11;
  const float* Vb = V + (size_t)bh * S_LEN * DH;
  float* Pr = P + (size_t)row * S_LEN;

  const size_t cbase = (size_t)row * CAP;
  const int cnt = g_rowcnt[row];
  // reset metadata for next graph replay (warp owns this row)
  if (lane == 0){ g_rowcnt[row] = 0; g_rowmax[row] = 0; }

  bool fast = false;
  float vals[CAP/32]; int idxs[CAP/32];
  int nchunk = 0;
  float vmax = -3.0e38f;
  if (cnt > 0 && cnt <= CAP){
    nchunk = (cnt + 31) >> 5;
    for (int c = 0; c < nchunk; c++){
      int i = (c << 5) + lane;
      float v = -3.0e38f; int id = 0;
      if (i < cnt){ id = g_cidx[cbase + i]; v = g_cval[cbase + i]; }
      vals[c] = v; idxs[c] = id;
      vmax = fmaxf(vmax, v);
    }
    #pragma unroll
    for (int off = 16; off; off >>= 1) vmax = fmaxf(vmax, __shfl_xor_sync(0xffffffffu, vmax, off));
    fast = (vmax >= 14.0f);
  }

  if (fast){
    // Zero the full P row (poisoned 0xAA before timing), then overwrite
    // candidate positions. __syncwarp orders the stores across lanes.
    {
      const float4 z4 = make_float4(0.f, 0.f, 0.f, 0.f);
      float4* Pr4 = (float4*)Pr;
      #pragma unroll
      for (int i = 0; i < 16; i++) Pr4[(i << 5) + lane] = z4;
    }
    __syncwarp();

    const float smaxv = expf(vmax) * 0.125f;
    float lsum = 0.0f;
    for (int c = 0; c < nchunk; c++){
      int i = (c << 5) + lane;
      float e = 0.0f;
      if (i < cnt){ e = expf(expf(vals[c]) * 0.125f - smaxv); lsum += e; }
      vals[c] = e;
    }
    #pragma unroll
    for (int off = 16; off; off >>= 1) lsum += __shfl_xor_sync(0xffffffffu, lsum, off);
    const float inv = 1.0f / lsum;

    float o0 = 0.0f, o1 = 0.0f;
    for (int c = 0; c < nchunk; c++){
      int i = (c << 5) + lane;
      float p = vals[c] * inv;
      if (i < cnt) Pr[idxs[c]] = p;
      unsigned mnz = __ballot_sync(0xffffffffu, (i < cnt) && (p != 0.0f));
      while (mnz){
        int src = __ffs(mnz) - 1; mnz &= mnz - 1;
        float pv = __shfl_sync(0xffffffffu, p, src);
        int  key = __shfl_sync(0xffffffffu, idxs[c], src);
        const float* vr = Vb + (size_t)key * DH;
        o0 += pv * vr[lane];
        o1 += pv * vr[lane + 32];
      }
    }
    Out[(size_t)row * DH + lane]      = o0;
    Out[(size_t)row * DH + lane + 32] = o1;
  } else {
    // ---- exact fallback (reference semantics), warp-only, 3-pass ----
    const float* Qr = Q + (size_t)row * DH;
    const float* Kb = K + (size_t)bh * S_LEN * DH;
    const int*   mrow = mask + (bh >> 3) * S_LEN;

    float mx = -3.0e38f;
    for (int key = lane; key < S_LEN; key += 32){
      float acc = 0.0f;
      #pragma unroll 16
      for (int d = 0; d < DH; d++) acc += Qr[d] * Kb[(size_t)key * DH + d];
      float qkv = mrow[key] ? acc : -1e9f;
      mx = fmaxf(mx, qkv);
    }
    #pragma unroll
    for (int off = 16; off; off >>= 1) mx = fmaxf(mx, __shfl_xor_sync(0xffffffffu, mx, off));
    const float qmax = mx;
    const float smax_s = (qmax <= -1e8f) ? -1e9f : expf(qmax) * 0.125f;

    float lsum = 0.0f;
    for (int key = lane; key < S_LEN; key += 32){
      float acc = 0.0f;
      #pragma unroll 16
      for (int d = 0; d < DH; d++) acc += Qr[d] * Kb[(size_t)key * DH + d];
      float qkv = mrow[key] ? acc : -1e9f;
      float s = (qkv <= -1e8f) ? -1e9f : expf(qkv) * 0.125f;
      lsum += expf(s - smax_s);
    }
    #pragma unroll
    for (int off = 16; off; off >>= 1) lsum += __shfl_xor_sync(0xffffffffu, lsum, off);
    const float inv = 1.0f / lsum;

    float o0 = 0.0f, o1 = 0.0f;
    for (int key0 = 0; key0 < S_LEN; key0 += 32){
      int key = key0 + lane;
      float acc = 0.0f;
      #pragma unroll 16
      for (int d = 0; d < DH; d++) acc += Qr[d] * Kb[(size_t)key * DH + d];
      float qkv = mrow[key] ? acc : -1e9f;
      float s = (qkv <= -1e8f) ? -1e9f : expf(qkv) * 0.125f;
      float p = expf(s - smax_s) * inv;
      Pr[key] = p;
      #pragma unroll
      for (int src = 0; src < 32; src++){
        float pv = __shfl_sync(0xffffffffu, p, src);
        if (pv != 0.0f){
          const float* vr = Vb + (size_t)(key0 + src) * DH;
          o0 += pv * vr[lane];
          o1 += pv * vr[lane + 32];
        }
      }
    }
    Out[(size_t)row * DH + lane]      = o0;
    Out[(size_t)row * DH + lane + 32] = o1;
  }
}

extern "C" void kernel_launch(void* const* d_in, const int* in_sizes, int n_in,
                              void* d_out, int out_size)
{
  const float* Q    = (const float*)d_in[0];
  const float* K    = (const float*)d_in[1];
  const float* V    = (const float*)d_in[2];
  const int*   mask = (const int*)d_in[3];

  float* Out = (float*)d_out;                        // (B,H,S,D)
  float* P   = Out + (size_t)NB * NH * S_LEN * DH;   // (B,H,S,S)

  const int smem = 512 + 2 * 128 * PT * 4;           // 70144 B
  cudaFuncSetAttribute(qk_mma, cudaFuncAttributeMaxDynamicSharedMemorySize, smem);
  cudaFuncSetAttribute(qk_mma, cudaFuncAttributePreferredSharedMemoryCarveout, 100);
  dim3 g1(S_LEN / 128, S_LEN / 128, NB * NH);        // 16 x 16 x 16
  qk_mma<<<g1, 256, smem>>>(Q, K, mask, P);

  scatter_pv<<<NROWS / 8, 256>>>(Q, K, V, mask, P, Out);
}

// round 10
// speedup vs baseline: 1.2023x; 1.2023x over previous
#include <cuda_runtime.h>
#include <stdint.h>
#include <math.h>

#define S_LEN 2048
#define NH    8
#define NB    2
#define DH    64
#define NROWS (NB*NH*S_LEN)   // 32768
#define CAP   256
#define PT    100             // smem pitch: 100 % 32 == 4 -> conflict-free frags

// ---- scratch (static device memory; zero-initialized at load) ----
__device__ int   g_rowmax[NROWS];
__device__ int   g_rowcnt[NROWS];
__device__ int   g_cidx[(size_t)NROWS * CAP];
__device__ float g_cval[(size_t)NROWS * CAP];

__device__ __forceinline__ uint32_t cvt_tf32(float x){
  uint32_t r;
  asm("cvt.rna.tf32.f32 %0, %1;" : "=r"(r) : "f"(x));
  return r;
}
__device__ __forceinline__ void mma_tf32(float* c, const uint32_t* a, uint32_t b0, uint32_t b1){
  asm volatile(
    "mma.sync.aligned.m16n8k8.row.col.f32.tf32.tf32.f32 "
    "{%0,%1,%2,%3}, {%4,%5,%6,%7}, {%8,%9}, {%0,%1,%2,%3};"
    : "+f"(c[0]), "+f"(c[1]), "+f"(c[2]), "+f"(c[3])
    : "r"(a[0]), "r"(a[1]), "r"(a[2]), "r"(a[3]), "r"(b0), "r"(b1));
}

// ===================== Kernel 1: tf32 mma.sync QK^T =====================
// Zeros its P tile with coalesced streaming stores (drain under the MMA),
// finds per-row approx max + candidates, recomputes candidates exactly.
__global__ __launch_bounds__(256, 2)
void qk_mma(const float* __restrict__ Q, const float* __restrict__ K,
            const int* __restrict__ mask, float* __restrict__ P)
{
  extern __shared__ char sm[];
  int* smask = (int*)sm;                                  // [128]
  uint32_t* Qs = (uint32_t*)(sm + 512);                   // [128][PT] tf32 bits
  uint32_t* Ks = (uint32_t*)(sm + 512 + 128 * PT * 4);    // [128][PT]

  const int bh = blockIdx.z;
  const int tm = blockIdx.y << 7;
  const int tn = blockIdx.x << 7;
  const int t = threadIdx.x;
  const int wid = t >> 5, lane = t & 31;
  const int wm = wid >> 1, wn = wid & 1;   // warps: 4 over M, 2 over N
  const int g  = lane >> 2, qd = lane & 3;
  const int b  = bh >> 3;
  const float* Qb = Q + ((size_t)bh * S_LEN + tm) * DH;
  const float* Kb = K + ((size_t)bh * S_LEN + tn) * DH;

  if (t < 128) smask[t] = mask[b * S_LEN + tn + t];

  // Coalesced zero of this CTA's 128x128 P tile: per pass, each warp writes
  // one contiguous 512B row segment (nL=4 per STG.128).
  {
    const float4 z4 = make_float4(0.f, 0.f, 0.f, 0.f);
    float* Pbase = P + ((size_t)bh * S_LEN + tm) * S_LEN + tn;
    #pragma unroll
    for (int p = 0; p < 16; p++){
      int row = (p << 3) + wid;
      *(float4*)(Pbase + (size_t)row * S_LEN + (lane << 2)) = z4;
    }
  }

  // Load tiles, convert to tf32 (rna) into smem.
  #pragma unroll
  for (int i = 0; i < 8; i++){
    int idx = (i << 8) + t;            // 0..2047
    int row = idx >> 4;
    int col = (idx & 15) << 2;
    float4 q = *(const float4*)(Qb + row * DH + col);
    float4 k = *(const float4*)(Kb + row * DH + col);
    uint32_t* qd_ = Qs + row * PT + col;
    qd_[0] = cvt_tf32(q.x); qd_[1] = cvt_tf32(q.y);
    qd_[2] = cvt_tf32(q.z); qd_[3] = cvt_tf32(q.w);
    uint32_t* kd_ = Ks + row * PT + col;
    kd_[0] = cvt_tf32(k.x); kd_[1] = cvt_tf32(k.y);
    kd_[2] = cvt_tf32(k.z); kd_[3] = cvt_tf32(k.w);
  }
  __syncthreads();

  // Accumulators: 2 m-tiles x 8 n-tiles x 4 regs (warp tile 32x64).
  float c[2][8][4];
  #pragma unroll
  for (int mt = 0; mt < 2; mt++)
    #pragma unroll
    for (int nt = 0; nt < 8; nt++)
      #pragma unroll
      for (int j = 0; j < 4; j++) c[mt][nt][j] = 0.0f;

  #pragma unroll
  for (int ks = 0; ks < 8; ks++){
    const int k0 = ks << 3;
    uint32_t a[2][4];
    #pragma unroll
    for (int mt = 0; mt < 2; mt++){
      int rbase = (wm << 5) + (mt << 4) + g;
      a[mt][0] = Qs[ rbase      * PT + k0 + qd];
      a[mt][1] = Qs[(rbase + 8) * PT + k0 + qd];
      a[mt][2] = Qs[ rbase      * PT + k0 + qd + 4];
      a[mt][3] = Qs[(rbase + 8) * PT + k0 + qd + 4];
    }
    #pragma unroll
    for (int nt = 0; nt < 8; nt++){
      int nbase = (wn << 6) + (nt << 3) + g;
      uint32_t b0 = Ks[nbase * PT + k0 + qd];
      uint32_t b1 = Ks[nbase * PT + k0 + qd + 4];
      mma_tf32(c[0][nt], a[0], b0, b1);
      mma_tf32(c[1][nt], a[1], b0, b1);
    }
  }

  // Epilogue: per-row approx max -> atomicMax -> flags -> exact recompute.
  float ths[2][2];
  unsigned fl[2] = {0u, 0u};
  #pragma unroll
  for (int mt = 0; mt < 2; mt++){
    #pragma unroll
    for (int rr = 0; rr < 2; rr++){
      const int r = (wm << 5) + (mt << 4) + (rr << 3) + g;
      float lmax = -1e9f;
      #pragma unroll
      for (int nt = 0; nt < 8; nt++){
        int cb = (wn << 6) + (nt << 3) + (qd << 1);
        float v0 = c[mt][nt][rr * 2 + 0];
        float v1 = c[mt][nt][rr * 2 + 1];
        if (smask[cb])     lmax = fmaxf(lmax, v0);
        if (smask[cb + 1]) lmax = fmaxf(lmax, v1);
      }
      lmax = fmaxf(lmax, __shfl_xor_sync(0xffffffffu, lmax, 1));
      lmax = fmaxf(lmax, __shfl_xor_sync(0xffffffffu, lmax, 2));
      const int grow = bh * S_LEN + tm + r;
      float newmax = 0.0f;
      if (qd == 0){
        int old = atomicMax(&g_rowmax[grow], __float_as_int(lmax));
        newmax = fmaxf(lmax, __int_as_float(old));
      }
      newmax = __shfl_sync(0xffffffffu, newmax, lane & ~3);
      ths[mt][rr] = newmax - 0.19f;   // 0.03 slack + 2 x 0.065 tf32 margin
    }
  }
  #pragma unroll
  for (int mt = 0; mt < 2; mt++)
    #pragma unroll
    for (int nt = 0; nt < 8; nt++)
      #pragma unroll
      for (int rr = 0; rr < 2; rr++)
        #pragma unroll
        for (int jj = 0; jj < 2; jj++){
          int cb = (wn << 6) + (nt << 3) + (qd << 1) + jj;
          unsigned pred = (smask[cb] && c[mt][nt][rr * 2 + jj] >= ths[mt][rr]) ? 1u : 0u;
          int bit = (mt << 5) + (nt << 2) + (rr << 1) + jj;
          fl[bit >> 5] |= pred << (bit & 31);
        }

  #pragma unroll
  for (int wdi = 0; wdi < 2; wdi++){
    unsigned bits = fl[wdi];
    while (bits){
      int p = __ffs(bits) - 1; bits &= bits - 1;
      int code = (wdi << 5) + p;
      int mt = code >> 5, rem = code & 31;
      int nt = rem >> 2, rr = (rem >> 1) & 1, jj = rem & 1;
      int r  = (wm << 5) + (mt << 4) + (rr << 3) + g;
      int cc = (wn << 6) + (nt << 3) + (qd << 1) + jj;
      // exact fp32 recompute from global (L1/L2-hot)
      const float* qr = Qb + r * DH;
      const float* kr = Kb + cc * DH;
      float acc = 0.0f;
      #pragma unroll 16
      for (int d = 0; d < DH; d++) acc += qr[d] * kr[d];
      float ap = c[mt][nt][rr * 2 + jj];
      // sanity gate: if the MMA path is broken, insert nothing -> exact fallback
      if (fabsf(acc - ap) <= 0.5f){
        int grow = bh * S_LEN + tm + r;
        int pos = atomicAdd(&g_rowcnt[grow], 1);
        if (pos < CAP){
          g_cidx[(size_t)grow * CAP + pos] = tn + cc;
          g_cval[(size_t)grow * CAP + pos] = acc;
        }
      }
    }
  }
}

// ============ Kernel 2: warp-per-row candidate softmax + PV ============
__global__ __launch_bounds__(256)
void scatter_pv(const float* __restrict__ Q, const float* __restrict__ K,
                const float* __restrict__ V, const int* __restrict__ mask,
                float* __restrict__ P, float* __restrict__ Out)
{
  const int wid  = threadIdx.x >> 5;
  const int lane = threadIdx.x & 31;
  const int row  = (blockIdx.x << 3) + wid;
  const int bh   = row >> 11;
  const float* Vb = V + (size_t)bh * S_LEN * DH;
  float* Pr = P + (size_t)row * S_LEN;

  const size_t cbase = (size_t)row * CAP;
  const int cnt = g_rowcnt[row];
  // reset metadata for next graph replay (warp owns this row)
  if (lane == 0){ g_rowcnt[row] = 0; g_rowmax[row] = 0; }

  bool fast = false;
  float vals[CAP/32]; int idxs[CAP/32];
  int nchunk = 0;
  float vmax = -3.0e38f;
  if (cnt > 0 && cnt <= CAP){
    nchunk = (cnt + 31) >> 5;
    for (int c = 0; c < nchunk; c++){
      int i = (c << 5) + lane;
      float v = -3.0e38f; int id = 0;
      if (i < cnt){ id = g_cidx[cbase + i]; v = g_cval[cbase + i]; }
      vals[c] = v; idxs[c] = id;
      vmax = fmaxf(vmax, v);
    }
    #pragma unroll
    for (int off = 16; off; off >>= 1) vmax = fmaxf(vmax, __shfl_xor_sync(0xffffffffu, vmax, off));
    fast = (vmax >= 14.0f);
  }

  if (fast){
    const float smaxv = expf(vmax) * 0.125f;
    float lsum = 0.0f;
    for (int c = 0; c < nchunk; c++){
      int i = (c << 5) + lane;
      float e = 0.0f;
      if (i < cnt){ e = expf(expf(vals[c]) * 0.125f - smaxv); lsum += e; }
      vals[c] = e;
    }
    #pragma unroll
    for (int off = 16; off; off >>= 1) lsum += __shfl_xor_sync(0xffffffffu, lsum, off);
    const float inv = 1.0f / lsum;

    float o0 = 0.0f, o1 = 0.0f;
    for (int c = 0; c < nchunk; c++){
      int i = (c << 5) + lane;
      float p = vals[c] * inv;
      if (i < cnt) Pr[idxs[c]] = p;
      unsigned mnz = __ballot_sync(0xffffffffu, (i < cnt) && (p != 0.0f));
      while (mnz){
        int src = __ffs(mnz) - 1; mnz &= mnz - 1;
        float pv = __shfl_sync(0xffffffffu, p, src);
        int  key = __shfl_sync(0xffffffffu, idxs[c], src);
        const float* vr = Vb + (size_t)key * DH;
        o0 += pv * vr[lane];
        o1 += pv * vr[lane + 32];
      }
    }
    Out[(size_t)row * DH + lane]      = o0;
    Out[(size_t)row * DH + lane + 32] = o1;
  } else {
    // ---- exact fallback (reference semantics), warp-only, 3-pass ----
    const float* Qr = Q + (size_t)row * DH;
    const float* Kb = K + (size_t)bh * S_LEN * DH;
    const int*   mrow = mask + (bh >> 3) * S_LEN;

    float mx = -3.0e38f;
    for (int key = lane; key < S_LEN; key += 32){
      float acc = 0.0f;
      #pragma unroll 16
      for (int d = 0; d < DH; d++) acc += Qr[d] * Kb[(size_t)key * DH + d];
      float qkv = mrow[key] ? acc : -1e9f;
      mx = fmaxf(mx, qkv);
    }
    #pragma unroll
    for (int off = 16; off; off >>= 1) mx = fmaxf(mx, __shfl_xor_sync(0xffffffffu, mx, off));
    const float qmax = mx;
    const float smax_s = (qmax <= -1e8f) ? -1e9f : expf(qmax) * 0.125f;

    float lsum = 0.0f;
    for (int key = lane; key < S_LEN; key += 32){
      float acc = 0.0f;
      #pragma unroll 16
      for (int d = 0; d < DH; d++) acc += Qr[d] * Kb[(size_t)key * DH + d];
      float qkv = mrow[key] ? acc : -1e9f;
      float s = (qkv <= -1e8f) ? -1e9f : expf(qkv) * 0.125f;
      lsum += expf(s - smax_s);
    }
    #pragma unroll
    for (int off = 16; off; off >>= 1) lsum += __shfl_xor_sync(0xffffffffu, lsum, off);
    const float inv = 1.0f / lsum;

    float o0 = 0.0f, o1 = 0.0f;
    for (int key0 = 0; key0 < S_LEN; key0 += 32){
      int key = key0 + lane;
      float acc = 0.0f;
      #pragma unroll 16
      for (int d = 0; d < DH; d++) acc += Qr[d] * Kb[(size_t)key * DH + d];
      float qkv = mrow[key] ? acc : -1e9f;
      float s = (qkv <= -1e8f) ? -1e9f : expf(qkv) * 0.125f;
      float p = expf(s - smax_s) * inv;
      Pr[key] = p;
      #pragma unroll
      for (int src = 0; src < 32; src++){
        float pv = __shfl_sync(0xffffffffu, p, src);
        if (pv != 0.0f){
          const float* vr = Vb + (size_t)(key0 + src) * DH;
          o0 += pv * vr[lane];
          o1 += pv * vr[lane + 32];
        }
      }
    }
    Out[(size_t)row * DH + lane]      = o0;
    Out[(size_t)row * DH + lane + 32] = o1;
  }
}

extern "C" void kernel_launch(void* const* d_in, const int* in_sizes, int n_in,
                              void* d_out, int out_size)
{
  const float* Q    = (const float*)d_in[0];
  const float* K    = (const float*)d_in[1];
  const float* V    = (const float*)d_in[2];
  const int*   mask = (const int*)d_in[3];

  float* Out = (float*)d_out;                        // (B,H,S,D)
  float* P   = Out + (size_t)NB * NH * S_LEN * DH;   // (B,H,S,S)

  const int smem = 512 + 2 * 128 * PT * 4;           // 102912 B
  cudaFuncSetAttribute(qk_mma, cudaFuncAttributeMaxDynamicSharedMemorySize, smem);
  cudaFuncSetAttribute(qk_mma, cudaFuncAttributePreferredSharedMemoryCarveout, 100);
  dim3 g1(S_LEN / 128, S_LEN / 128, NB * NH);        // 16 x 16 x 16
  qk_mma<<<g1, 256, smem>>>(Q, K, mask, P);

  scatter_pv<<<NROWS / 8, 256>>>(Q, K, V, mask, P, Out);
}